// round 3
// baseline (speedup 1.0000x reference)
#include <cuda_runtime.h>
#include <math.h>
#include <stdint.h>

// Problem constants
#define T_TOK 4096
#define D_DIM 512
#define E_NUM 8
#define F_DIM 2048
#define DF_DIM 64
#define CAP   9216          // 72 * 128 : 2T=8192 assigned slots + worst-case per-expert 128-pad
#define MTILES 72           // CAP / 128
#define RBLOCKS 512         // router blocks (8 tokens each)

// ---------------- scratch (device globals; no allocation allowed) ----------------
__device__ int   g_counts[E_NUM];
__device__ int   g_fill[E_NUM];
__device__ int   g_offpad[E_NUM + 1];
__device__ int   g_tile_expert[MTILES];
__device__ int   g_slot_token[CAP];
__device__ int   g_slot_expert[CAP];
__device__ float g_slot_w[CAP];
__device__ int   g_token_slot[T_TOK * 2];
__device__ int   g_tok_idx[T_TOK * 2];
__device__ float g_tok_w[T_TOK * 2];
__device__ float g_probs_partial[RBLOCKS * E_NUM];
__device__ float g_xg[CAP * D_DIM];                 // gathered expert inputs (+side terms)
__device__ float g_h[CAP * F_DIM];                  // gelu(x@W1+b1)
__device__ float g_outs[CAP * D_DIM];               // h@W2 (no bias)

__device__ __forceinline__ float gelu_tanh(float v) {
    // jax.nn.gelu default: approximate=True (tanh form)
    float c = 0.7978845608028654f * (v + 0.044715f * v * v * v);
    return 0.5f * v * (1.0f + tanhf(c));
}

// ---------------- init: counters + slot tokens ----------------
__global__ void init_kernel() {
    int i = blockIdx.x * 256 + threadIdx.x;
    if (i < CAP) g_slot_token[i] = -1;
    if (i < E_NUM) { g_counts[i] = 0; g_fill[i] = 0; }
}

// ---------------- router: logits -> softmax -> top2, deterministic prob partials ----------------
__global__ __launch_bounds__(256) void router_kernel(const float* __restrict__ x,
                                                     const float* __restrict__ Wr) {
    __shared__ float sWr[D_DIM * E_NUM];   // 16 KB
    __shared__ float sprobs[8][E_NUM];
    int tid = threadIdx.x;
    #pragma unroll
    for (int i = tid; i < D_DIM * E_NUM; i += 256) sWr[i] = Wr[i];
    __syncthreads();

    int warp = tid >> 5, lane = tid & 31;
    int t = blockIdx.x * 8 + warp;
    const float* xr = x + (size_t)t * D_DIM;

    float acc[E_NUM];
    #pragma unroll
    for (int e = 0; e < E_NUM; e++) acc[e] = 0.f;
    for (int k = lane; k < D_DIM; k += 32) {
        float xv = xr[k];
        const float* w = sWr + k * E_NUM;
        #pragma unroll
        for (int e = 0; e < E_NUM; e++) acc[e] += xv * w[e];
    }
    #pragma unroll
    for (int e = 0; e < E_NUM; e++) {
        float v = acc[e];
        #pragma unroll
        for (int off = 16; off >= 1; off >>= 1) v += __shfl_xor_sync(0xffffffffu, v, off);
        acc[e] = v;
    }
    if (lane == 0) {
        float mx = acc[0];
        #pragma unroll
        for (int e = 1; e < E_NUM; e++) mx = fmaxf(mx, acc[e]);
        float p[E_NUM]; float s = 0.f;
        #pragma unroll
        for (int e = 0; e < E_NUM; e++) { p[e] = expf(acc[e] - mx); s += p[e]; }
        float inv = 1.f / s;
        #pragma unroll
        for (int e = 0; e < E_NUM; e++) p[e] *= inv;
        // top-2 with jax tie-break (lowest index wins ties -> strict >)
        int i0 = 0;
        #pragma unroll
        for (int e = 1; e < E_NUM; e++) if (p[e] > p[i0]) i0 = e;
        int i1 = -1;
        #pragma unroll
        for (int e = 0; e < E_NUM; e++) {
            if (e == i0) continue;
            if (i1 < 0 || p[e] > p[i1]) i1 = e;
        }
        float w0 = p[i0], w1 = p[i1];
        float wn = 1.f / (w0 + w1);
        g_tok_idx[2 * t + 0] = i0; g_tok_w[2 * t + 0] = w0 * wn;
        g_tok_idx[2 * t + 1] = i1; g_tok_w[2 * t + 1] = w1 * wn;
        atomicAdd(&g_counts[i0], 1);
        atomicAdd(&g_counts[i1], 1);
        #pragma unroll
        for (int e = 0; e < E_NUM; e++) sprobs[warp][e] = p[e];
    }
    __syncthreads();
    if (tid < E_NUM) {
        float s = 0.f;
        #pragma unroll
        for (int w = 0; w < 8; w++) s += sprobs[w][tid];
        g_probs_partial[blockIdx.x * E_NUM + tid] = s;
    }
}

// ---------------- scan: padded offsets, tile->expert map, aux loss ----------------
__global__ void scan_kernel(float* aux_out) {
    __shared__ float psum[E_NUM];
    int tid = threadIdx.x;
    if (tid < E_NUM) {
        float s = 0.f;
        for (int b = 0; b < RBLOCKS; b++) s += g_probs_partial[b * E_NUM + tid];
        psum[tid] = s;
    }
    __syncthreads();
    if (tid == 0) {
        int off = 0;
        for (int e = 0; e < E_NUM; e++) {
            g_offpad[e] = off;
            off += ((g_counts[e] + 127) / 128) * 128;
        }
        g_offpad[E_NUM] = off;
        for (int tile = 0; tile < MTILES; tile++) {
            int row = tile * 128;
            int ex = E_NUM - 1;
            for (int q = 0; q < E_NUM; q++) {
                if (row >= g_offpad[q] && row < g_offpad[q + 1]) { ex = q; break; }
            }
            g_tile_expert[tile] = ex;
        }
        float aux = 0.f;
        for (int e = 0; e < E_NUM; e++)
            aux += ((float)g_counts[e] / (float)T_TOK) * (psum[e] / (float)T_TOK);
        aux *= (float)E_NUM;
        if (aux_out) aux_out[0] = aux;
    }
}

// ---------------- assign: token -> slot (int atomics only) ----------------
__global__ void assign_kernel() {
    int t = blockIdx.x * 256 + threadIdx.x;
    if (t >= T_TOK) return;
    #pragma unroll
    for (int j = 0; j < 2; j++) {
        int e = g_tok_idx[2 * t + j];
        int pos = atomicAdd(&g_fill[e], 1);
        int s = g_offpad[e] + pos;
        g_slot_token[s] = t;
        g_slot_expert[s] = e;
        g_slot_w[s] = g_tok_w[2 * t + j];
        g_token_slot[2 * t + j] = s;
    }
}

// ---------------- gather: xg[slot] = x[t] (+ side term), pads -> 0 ----------------
__global__ __launch_bounds__(128) void gather_kernel(const float* __restrict__ x,
                                                     const float* __restrict__ flow,
                                                     const float* __restrict__ avgq,
                                                     const float* __restrict__ deltas,
                                                     const float* __restrict__ Wf,
                                                     const float* __restrict__ Wd) {
    __shared__ float side[DF_DIM];
    int slot = blockIdx.x;
    int t = g_slot_token[slot];
    float4* dst = (float4*)(g_xg + (size_t)slot * D_DIM);
    int d4 = threadIdx.x;              // 128 threads * float4 = 512
    if (t < 0) { dst[d4] = make_float4(0.f, 0.f, 0.f, 0.f); return; }
    int e = g_slot_expert[slot];
    float4 v = ((const float4*)(x + (size_t)t * D_DIM))[d4];
    if (e == 0 || e == 4) {
        const float* srow = (e == 0 ? flow : deltas) + (size_t)t * DF_DIM;
        if (threadIdx.x < DF_DIM) side[threadIdx.x] = srow[threadIdx.x];
        __syncthreads();
        const float* W = (e == 0 ? Wf : Wd);
        int d0 = d4 * 4;
        #pragma unroll 8
        for (int k = 0; k < DF_DIM; k++) {
            float s = side[k];
            float4 w = *(const float4*)(W + (size_t)k * D_DIM + d0);
            v.x += s * w.x; v.y += s * w.y; v.z += s * w.z; v.w += s * w.w;
        }
    } else if (e == 3) {
        float4 q = ((const float4*)(avgq + (size_t)t * D_DIM))[d4];
        v.x += q.x; v.y += q.y; v.z += q.z; v.w += q.w;
    }
    dst[d4] = v;
}

// ---------------- grouped SGEMM 128x128x8, double-buffered smem, fused bias+gelu ----------------
template <bool FIRST>
__global__ __launch_bounds__(256) void gemm_kernel(const float* __restrict__ Bw,
                                                   const float* __restrict__ bias) {
    constexpr int K = FIRST ? D_DIM : F_DIM;
    constexpr int N = FIRST ? F_DIM : D_DIM;
    constexpr int NITER = K / 8;
    const float* A = FIRST ? g_xg : g_h;
    float*       C = FIRST ? g_h  : g_outs;

    __shared__ float As[2][8][128];
    __shared__ float Bs[2][8][128];

    const int tid = threadIdx.x;
    const int mtile = blockIdx.y, ntile = blockIdx.x;
    const int e = g_tile_expert[mtile];

    const float* Ab = A + (size_t)mtile * 128 * K;
    const float* Bb = Bw + (size_t)e * K * N + (size_t)ntile * 128;

    const int aRow = tid >> 1, aCol = (tid & 1) * 4;      // 128x8 A tile, float4/thread
    const int bRow = tid >> 5, bCol = (tid & 31) * 4;     // 8x128 B tile, float4/thread
    const int mthr = (tid >> 4) * 8, nthr = (tid & 15) * 8;

    float acc[8][8];
    #pragma unroll
    for (int i = 0; i < 8; i++)
        #pragma unroll
        for (int j = 0; j < 8; j++) acc[i][j] = 0.f;

    // prologue: load tile 0 into buffer 0
    {
        float4 av = *(const float4*)(Ab + (size_t)aRow * K + aCol);
        float4 bv = *(const float4*)(Bb + (size_t)bRow * N + bCol);
        As[0][aCol + 0][aRow] = av.x;
        As[0][aCol + 1][aRow] = av.y;
        As[0][aCol + 2][aRow] = av.z;
        As[0][aCol + 3][aRow] = av.w;
        *(float4*)&Bs[0][bRow][bCol] = bv;
    }
    __syncthreads();

    for (int it = 0; it < NITER; it++) {
        const int buf = it & 1;
        float4 av, bv;
        if (it + 1 < NITER) {
            int k0 = (it + 1) * 8;
            av = *(const float4*)(Ab + (size_t)aRow * K + (k0 + aCol));
            bv = *(const float4*)(Bb + (size_t)(k0 + bRow) * N + bCol);
        }
        #pragma unroll
        for (int kk = 0; kk < 8; kk++) {
            float4 a0 = *(const float4*)&As[buf][kk][mthr];
            float4 a1 = *(const float4*)&As[buf][kk][mthr + 4];
            float4 b0 = *(const float4*)&Bs[buf][kk][nthr];
            float4 b1 = *(const float4*)&Bs[buf][kk][nthr + 4];
            float am[8] = {a0.x, a0.y, a0.z, a0.w, a1.x, a1.y, a1.z, a1.w};
            float bn[8] = {b0.x, b0.y, b0.z, b0.w, b1.x, b1.y, b1.z, b1.w};
            #pragma unroll
            for (int i = 0; i < 8; i++)
                #pragma unroll
                for (int j = 0; j < 8; j++) acc[i][j] += am[i] * bn[j];
        }
        if (it + 1 < NITER) {
            const int nb = buf ^ 1;
            As[nb][aCol + 0][aRow] = av.x;
            As[nb][aCol + 1][aRow] = av.y;
            As[nb][aCol + 2][aRow] = av.z;
            As[nb][aCol + 3][aRow] = av.w;
            *(float4*)&Bs[nb][bRow][bCol] = bv;
            __syncthreads();
        }
    }

    float bloc[8];
    if (FIRST) {
        #pragma unroll
        for (int j = 0; j < 8; j++) bloc[j] = bias[(size_t)e * N + ntile * 128 + nthr + j];
    }
    #pragma unroll
    for (int i = 0; i < 8; i++) {
        float* crow = C + (size_t)(mtile * 128 + mthr + i) * N + ntile * 128 + nthr;
        float v[8];
        #pragma unroll
        for (int j = 0; j < 8; j++) {
            float t = acc[i][j];
            if (FIRST) t = gelu_tanh(t + bloc[j]);
            v[j] = t;
        }
        *(float4*)(crow)     = make_float4(v[0], v[1], v[2], v[3]);
        *(float4*)(crow + 4) = make_float4(v[4], v[5], v[6], v[7]);
    }
}

// ---------------- combine: final[t] = w0*(out[s0]+b2[e0]) + w1*(out[s1]+b2[e1]) ----------------
__global__ __launch_bounds__(128) void combine_kernel(const float* __restrict__ b2,
                                                      float* __restrict__ out) {
    int t = blockIdx.x;
    int d4 = threadIdx.x;  // 128 threads * float4 = 512
    int s0 = g_token_slot[2 * t + 0];
    int s1 = g_token_slot[2 * t + 1];
    int e0 = g_slot_expert[s0], e1 = g_slot_expert[s1];
    float w0 = g_slot_w[s0], w1 = g_slot_w[s1];
    float4 o0 = ((const float4*)(g_outs + (size_t)s0 * D_DIM))[d4];
    float4 o1 = ((const float4*)(g_outs + (size_t)s1 * D_DIM))[d4];
    float4 c0 = ((const float4*)(b2 + (size_t)e0 * D_DIM))[d4];
    float4 c1 = ((const float4*)(b2 + (size_t)e1 * D_DIM))[d4];
    float4 r;
    r.x = w0 * (o0.x + c0.x) + w1 * (o1.x + c1.x);
    r.y = w0 * (o0.y + c0.y) + w1 * (o1.y + c1.y);
    r.z = w0 * (o0.z + c0.z) + w1 * (o1.z + c1.z);
    r.w = w0 * (o0.w + c0.w) + w1 * (o1.w + c1.w);
    ((float4*)(out + (size_t)t * D_DIM))[d4] = r;
}

// ---------------- launch ----------------
extern "C" void kernel_launch(void* const* d_in, const int* in_sizes, int n_in,
                              void* d_out, int out_size) {
    const float* x      = (const float*)d_in[0];
    const float* flow   = (const float*)d_in[1];
    const float* avgq   = (const float*)d_in[2];
    const float* deltas = (const float*)d_in[3];
    const float* Wr     = (const float*)d_in[4];
    const float* W1     = (const float*)d_in[5];
    const float* b1     = (const float*)d_in[6];
    const float* W2     = (const float*)d_in[7];
    const float* b2     = (const float*)d_in[8];
    const float* Wf     = (const float*)d_in[9];
    const float* Wd     = (const float*)d_in[10];
    float* out = (float*)d_out;

    float* aux_ptr = (out_size > T_TOK * D_DIM) ? (out + (size_t)T_TOK * D_DIM) : nullptr;

    init_kernel<<<(CAP + 255) / 256, 256>>>();
    router_kernel<<<RBLOCKS, 256>>>(x, Wr);
    scan_kernel<<<1, 256>>>(aux_ptr);
    assign_kernel<<<(T_TOK + 255) / 256, 256>>>();
    gather_kernel<<<CAP, 128>>>(x, flow, avgq, deltas, Wf, Wd);
    gemm_kernel<true><<<dim3(F_DIM / 128, MTILES), 256>>>(W1, b1);
    gemm_kernel<false><<<dim3(D_DIM / 128, MTILES), 256>>>(W2, nullptr);
    combine_kernel<<<T_TOK, 128>>>(b2, out);
}

// round 9
// speedup vs baseline: 2.0394x; 2.0394x over previous
#include <cuda_runtime.h>
#include <cuda_bf16.h>
#include <math.h>
#include <stdint.h>

// Problem constants
#define T_TOK 4096
#define D_DIM 512
#define E_NUM 8
#define F_DIM 2048
#define DF_DIM 64
#define CAP   9216          // 72*128: 2T=8192 slots + worst-case per-expert 128-pad
#define MTILES 72
#define RBLOCKS 512

// SMEM stage: A tile 16KB ([m=128][128B: hi64|lo64]) + Bhi 8KB + Blo 8KB ([k=32][256B])
#define A_TILE_BYTES 16384
#define B_TILE_BYTES 8192
#define STAGE_BYTES (A_TILE_BYTES + 2*B_TILE_BYTES)   // 32KB
#define DSMEM_BYTES (2*STAGE_BYTES)                    // 64KB double-buffered

// ---------------- scratch (device globals) — total 113.4 MB, same as passing R3 ----------------
__device__ int   g_counts[E_NUM];
__device__ int   g_fill[E_NUM];
__device__ int   g_offpad[E_NUM + 1];
__device__ int   g_tile_expert[MTILES];
__device__ int   g_slot_token[CAP];
__device__ int   g_slot_expert[CAP];
__device__ float g_slot_w[CAP];
__device__ int   g_token_slot[T_TOK * 2];
__device__ int   g_tok_idx[T_TOK * 2];
__device__ float g_tok_w[T_TOK * 2];
__device__ float g_probs_partial[RBLOCKS * E_NUM];

__device__ __align__(16) __nv_bfloat16 g_ah[CAP * D_DIM];   // gathered x (+side), bf16 hi
__device__ __align__(16) __nv_bfloat16 g_al[CAP * D_DIM];   // lo residual
__device__ __align__(16) __nv_bfloat16 g_hh[CAP * F_DIM];   // gelu output hi
__device__ __align__(16) __nv_bfloat16 g_hl[CAP * F_DIM];   // gelu output lo
__device__ __align__(16) float g_outs[CAP * D_DIM];         // GEMM2 result (no bias)

// ---------------- helpers ----------------
__device__ __forceinline__ uint32_t smem_u32(const void* p) {
    uint32_t a;
    asm("{ .reg .u64 t; cvta.to.shared.u64 t, %1; cvt.u32.u64 %0, t; }" : "=r"(a) : "l"(p));
    return a;
}
#define SWZ128(o) ((o) ^ (((o) >> 3) & 0x70))

#define LDSM4(r, addr) \
    asm volatile("ldmatrix.sync.aligned.m8n8.x4.shared.b16 {%0,%1,%2,%3}, [%4];" \
        : "=r"((r)[0]), "=r"((r)[1]), "=r"((r)[2]), "=r"((r)[3]) : "r"(addr))
#define LDSM2T(r, addr) \
    asm volatile("ldmatrix.sync.aligned.m8n8.x2.trans.shared.b16 {%0,%1}, [%2];" \
        : "=r"((r)[0]), "=r"((r)[1]) : "r"(addr))
#define MMA_BF16(d, a, b) \
    asm volatile("mma.sync.aligned.m16n8k16.row.col.f32.bf16.bf16.f32 " \
        "{%0,%1,%2,%3}, {%4,%5,%6,%7}, {%8,%9}, {%0,%1,%2,%3};" \
        : "+f"((d)[0]), "+f"((d)[1]), "+f"((d)[2]), "+f"((d)[3]) \
        : "r"((a)[0]), "r"((a)[1]), "r"((a)[2]), "r"((a)[3]), "r"((b)[0]), "r"((b)[1]))
#define CP_ASYNC16(dst, src) \
    asm volatile("cp.async.cg.shared.global [%0], [%1], 16;" :: "r"(dst), "l"(src) : "memory")
#define CP_COMMIT() asm volatile("cp.async.commit_group;" ::: "memory")
#define CP_WAIT(n)  asm volatile("cp.async.wait_group %0;" :: "n"(n) : "memory")

__device__ __forceinline__ float gelu_tanh(float v) {
    float c = 0.7978845608028654f * (v + 0.044715f * v * v * v);
    return 0.5f * v * (1.0f + tanhf(c));
}

// ---------------- init ----------------
__global__ void init_kernel() {
    int i = blockIdx.x * 256 + threadIdx.x;
    if (i < CAP) g_slot_token[i] = -1;
    if (i < E_NUM) { g_counts[i] = 0; g_fill[i] = 0; }
}

// ---------------- router ----------------
__global__ __launch_bounds__(256) void router_kernel(const float* __restrict__ x,
                                                     const float* __restrict__ Wr) {
    __shared__ float sWr[D_DIM * E_NUM];
    __shared__ float sprobs[8][E_NUM];
    int tid = threadIdx.x;
    #pragma unroll
    for (int i = tid; i < D_DIM * E_NUM; i += 256) sWr[i] = Wr[i];
    __syncthreads();

    int warp = tid >> 5, lane = tid & 31;
    int t = blockIdx.x * 8 + warp;
    const float* xr = x + (size_t)t * D_DIM;

    float acc[E_NUM];
    #pragma unroll
    for (int e = 0; e < E_NUM; e++) acc[e] = 0.f;
    for (int k = lane; k < D_DIM; k += 32) {
        float xv = xr[k];
        const float* w = sWr + k * E_NUM;
        #pragma unroll
        for (int e = 0; e < E_NUM; e++) acc[e] += xv * w[e];
    }
    #pragma unroll
    for (int e = 0; e < E_NUM; e++) {
        float v = acc[e];
        #pragma unroll
        for (int off = 16; off >= 1; off >>= 1) v += __shfl_xor_sync(0xffffffffu, v, off);
        acc[e] = v;
    }
    if (lane == 0) {
        float mx = acc[0];
        #pragma unroll
        for (int e = 1; e < E_NUM; e++) mx = fmaxf(mx, acc[e]);
        float p[E_NUM]; float s = 0.f;
        #pragma unroll
        for (int e = 0; e < E_NUM; e++) { p[e] = expf(acc[e] - mx); s += p[e]; }
        float inv = 1.f / s;
        #pragma unroll
        for (int e = 0; e < E_NUM; e++) p[e] *= inv;
        int i0 = 0;
        #pragma unroll
        for (int e = 1; e < E_NUM; e++) if (p[e] > p[i0]) i0 = e;
        int i1 = -1;
        #pragma unroll
        for (int e = 0; e < E_NUM; e++) {
            if (e == i0) continue;
            if (i1 < 0 || p[e] > p[i1]) i1 = e;
        }
        float w0 = p[i0], w1 = p[i1];
        float wn = 1.f / (w0 + w1);
        g_tok_idx[2 * t + 0] = i0; g_tok_w[2 * t + 0] = w0 * wn;
        g_tok_idx[2 * t + 1] = i1; g_tok_w[2 * t + 1] = w1 * wn;
        atomicAdd(&g_counts[i0], 1);
        atomicAdd(&g_counts[i1], 1);
        #pragma unroll
        for (int e = 0; e < E_NUM; e++) sprobs[warp][e] = p[e];
    }
    __syncthreads();
    if (tid < E_NUM) {
        float s = 0.f;
        #pragma unroll
        for (int w = 0; w < 8; w++) s += sprobs[w][tid];
        g_probs_partial[blockIdx.x * E_NUM + tid] = s;
    }
}

// ---------------- scan ----------------
__global__ void scan_kernel(float* aux_out) {
    __shared__ float psum[E_NUM];
    int tid = threadIdx.x;
    if (tid < E_NUM) {
        float s = 0.f;
        for (int b = 0; b < RBLOCKS; b++) s += g_probs_partial[b * E_NUM + tid];
        psum[tid] = s;
    }
    __syncthreads();
    if (tid == 0) {
        int off = 0;
        for (int e = 0; e < E_NUM; e++) {
            g_offpad[e] = off;
            off += ((g_counts[e] + 127) / 128) * 128;
        }
        g_offpad[E_NUM] = off;
        for (int tile = 0; tile < MTILES; tile++) {
            int row = tile * 128;
            int ex = E_NUM - 1;
            for (int q = 0; q < E_NUM; q++) {
                if (row >= g_offpad[q] && row < g_offpad[q + 1]) { ex = q; break; }
            }
            g_tile_expert[tile] = ex;
        }
        float aux = 0.f;
        for (int e = 0; e < E_NUM; e++)
            aux += ((float)g_counts[e] / (float)T_TOK) * (psum[e] / (float)T_TOK);
        aux *= (float)E_NUM;
        if (aux_out) aux_out[0] = aux;
    }
}

// ---------------- assign ----------------
__global__ void assign_kernel() {
    int t = blockIdx.x * 256 + threadIdx.x;
    if (t >= T_TOK) return;
    #pragma unroll
    for (int j = 0; j < 2; j++) {
        int e = g_tok_idx[2 * t + j];
        int pos = atomicAdd(&g_fill[e], 1);
        int s = g_offpad[e] + pos;
        g_slot_token[s] = t;
        g_slot_expert[s] = e;
        g_slot_w[s] = g_tok_w[2 * t + j];
        g_token_slot[2 * t + j] = s;
    }
}

// ---------------- gather: xg[slot] -> bf16 hi/lo ----------------
__global__ __launch_bounds__(128) void gather_kernel(const float* __restrict__ x,
                                                     const float* __restrict__ flow,
                                                     const float* __restrict__ avgq,
                                                     const float* __restrict__ deltas,
                                                     const float* __restrict__ Wf,
                                                     const float* __restrict__ Wd) {
    __shared__ float side[DF_DIM];
    int slot = blockIdx.x;
    int t = g_slot_token[slot];
    int d4 = threadIdx.x;  // 128 threads * 4 elems
    uint2* dsth = (uint2*)(g_ah + (size_t)slot * D_DIM + d4 * 4);
    uint2* dstl = (uint2*)(g_al + (size_t)slot * D_DIM + d4 * 4);
    if (t < 0) {
        *dsth = make_uint2(0u, 0u);
        *dstl = make_uint2(0u, 0u);
        return;
    }
    int e = g_slot_expert[slot];
    float4 v = ((const float4*)(x + (size_t)t * D_DIM))[d4];
    if (e == 0 || e == 4) {
        const float* srow = (e == 0 ? flow : deltas) + (size_t)t * DF_DIM;
        if (threadIdx.x < DF_DIM) side[threadIdx.x] = srow[threadIdx.x];
        __syncthreads();
        const float* W = (e == 0 ? Wf : Wd);
        int d0 = d4 * 4;
        #pragma unroll 8
        for (int k = 0; k < DF_DIM; k++) {
            float s = side[k];
            float4 w = *(const float4*)(W + (size_t)k * D_DIM + d0);
            v.x += s * w.x; v.y += s * w.y; v.z += s * w.z; v.w += s * w.w;
        }
    } else if (e == 3) {
        float4 q = ((const float4*)(avgq + (size_t)t * D_DIM))[d4];
        v.x += q.x; v.y += q.y; v.z += q.z; v.w += q.w;
    }
    __nv_bfloat162 h01 = __floats2bfloat162_rn(v.x, v.y);
    __nv_bfloat162 h23 = __floats2bfloat162_rn(v.z, v.w);
    __nv_bfloat162 l01 = __floats2bfloat162_rn(v.x - __bfloat162float(__low2bfloat16(h01)),
                                               v.y - __bfloat162float(__high2bfloat16(h01)));
    __nv_bfloat162 l23 = __floats2bfloat162_rn(v.z - __bfloat162float(__low2bfloat16(h23)),
                                               v.w - __bfloat162float(__high2bfloat16(h23)));
    *dsth = make_uint2(*(uint32_t*)&h01, *(uint32_t*)&h23);
    *dstl = make_uint2(*(uint32_t*)&l01, *(uint32_t*)&l23);
}

// ---------------- grouped GEMM via mma.sync m16n8k16 bf16, 3-term split ----------------
// Block: 256 thr = 8 warps (2m x 4n), warp tile 64x32, block tile 128x128, K-chunk 32.
// A: cp.async bf16 hi/lo, SMEM [m=128][128B hi|lo] SW128, non-trans ldmatrix.x4.
// B: fp32 weights loaded directly, converted to bf16 hi/lo in-flight,
//    SMEM [k=32][256B n-major], per-row XOR swizzle byte(k,Y) = k*256 + (Y ^ ((k&7)<<4)),
//    read with ldmatrix.x2.trans.
// W layout: [E][KTOT][NTOT], n contiguous (W1: K=D,N=F;  W2: K=F,N=D).
template <int KTOT, bool FIRST>
__global__ __launch_bounds__(256) void gemm_mma(const float* __restrict__ Wsrc,
                                                const float* __restrict__ bias) {
    constexpr int NTOT = FIRST ? F_DIM : D_DIM;
    constexpr int NCH = KTOT / 32;
    extern __shared__ char dsm[];

    const int tid = threadIdx.x;
    const int wid = tid >> 5, lane = tid & 31;
    const int wm = wid >> 2, wn = wid & 3;       // 2x4 warp grid
    const int ntile = blockIdx.x, mtile = blockIdx.y;
    const int e = g_tile_expert[mtile];

    const __nv_bfloat16* Ah = (FIRST ? g_ah : g_hh) + (size_t)(mtile * 128) * KTOT;
    const __nv_bfloat16* Al = (FIRST ? g_al : g_hl) + (size_t)(mtile * 128) * KTOT;
    const float* Bw = Wsrc + (size_t)e * KTOT * NTOT + ntile * 128;   // [k][n] fp32, n contig

    const uint32_t smb = smem_u32(dsm);

    // ---- A staging plan (cp.async): thread t covers 4 units of 16B.
    const int r0  = tid >> 3;        // 0..31
    const int sub = tid & 7;
    const int halfA = sub >> 2, ku = sub & 3;
    const __nv_bfloat16* pA = (halfA ? Al : Ah) + (size_t)r0 * KTOT + ku * 8;
    const uint32_t dA0 = SWZ128((uint32_t)(r0 * 128 + halfA * 64 + ku * 16));
    // SWZ128 invariant under +4096 (row += 32): dst_i = dA0 + i*4096.

    // ---- B staging plan (LDG fp32 + convert + STS): thread t covers row krow, 4 float4s.
    const int krow = tid >> 3;       // 0..31
    const int seg  = tid & 7;        // n-start (floats) = seg*4 + c4*32
    const float* pB = Bw + (size_t)krow * NTOT + seg * 4;
    const uint32_t dBrow = (uint32_t)(krow * 256);
    const uint32_t maskB = ((uint32_t)(krow & 7)) << 4;
    // 8B store for segment c4 at: dBrow + ((seg*8 + c4*64) ^ maskB)   [always < 256]

    float acc[4][4][4];
    #pragma unroll
    for (int mf = 0; mf < 4; mf++)
        #pragma unroll
        for (int nf = 0; nf < 4; nf++)
            #pragma unroll
            for (int k = 0; k < 4; k++) acc[mf][nf][k] = 0.f;

    // ---- prologue: chunk 0 -> buffer 0
    {
        #pragma unroll
        for (int i = 0; i < 4; i++)
            CP_ASYNC16(smb + dA0 + i * 4096, pA + (size_t)i * 32 * KTOT);
        CP_COMMIT();
        char* bh = dsm + A_TILE_BYTES;
        char* bl = bh + B_TILE_BYTES;
        #pragma unroll
        for (int c4 = 0; c4 < 4; c4++) {
            float4 f = *(const float4*)(pB + c4 * 32);
            __nv_bfloat162 h01 = __floats2bfloat162_rn(f.x, f.y);
            __nv_bfloat162 h23 = __floats2bfloat162_rn(f.z, f.w);
            __nv_bfloat162 l01 = __floats2bfloat162_rn(f.x - __bfloat162float(__low2bfloat16(h01)),
                                                       f.y - __bfloat162float(__high2bfloat16(h01)));
            __nv_bfloat162 l23 = __floats2bfloat162_rn(f.z - __bfloat162float(__low2bfloat16(h23)),
                                                       f.w - __bfloat162float(__high2bfloat16(h23)));
            uint32_t off = dBrow + (((uint32_t)(seg * 8 + c4 * 64)) ^ maskB);
            *(uint2*)(bh + off) = make_uint2(*(uint32_t*)&h01, *(uint32_t*)&h23);
            *(uint2*)(bl + off) = make_uint2(*(uint32_t*)&l01, *(uint32_t*)&l23);
        }
        CP_WAIT(0);
    }
    __syncthreads();

    #pragma unroll 1
    for (int c = 0; c < NCH; c++) {
        const int buf = c & 1;
        float4 bq0, bq1, bq2, bq3;
        if (c + 1 < NCH) {
            const uint32_t nbA = smb + (buf ^ 1) * STAGE_BYTES;
            #pragma unroll
            for (int i = 0; i < 4; i++)
                CP_ASYNC16(nbA + dA0 + i * 4096, pA + (size_t)i * 32 * KTOT + (c + 1) * 32);
            CP_COMMIT();
            const float* pBn = pB + (size_t)(c + 1) * 32 * NTOT;
            bq0 = *(const float4*)(pBn);
            bq1 = *(const float4*)(pBn + 32);
            bq2 = *(const float4*)(pBn + 64);
            bq3 = *(const float4*)(pBn + 96);
        }

        // ---- compute chunk c
        const uint32_t At  = smb + buf * STAGE_BYTES;
        const uint32_t Bth = At + A_TILE_BYTES;
        const uint32_t Btl = Bth + B_TILE_BYTES;
        #pragma unroll
        for (int s = 0; s < 2; s++) {
            uint32_t ah[4][4], al[4][4];
            #pragma unroll
            for (int mf = 0; mf < 4; mf++) {
                int row = wm * 64 + mf * 16 + (lane & 15);
                int u = lane >> 4;
                uint32_t off = (uint32_t)(row * 128 + s * 32 + u * 16);
                LDSM4(ah[mf], At + SWZ128(off));
                LDSM4(al[mf], At + SWZ128(off + 64));
            }
            #pragma unroll
            for (int nf = 0; nf < 4; nf++) {
                uint32_t bh[2], bl[2];
                int kk = s * 16 + (lane & 15);
                uint32_t boff = (uint32_t)(kk * 256) +
                                (((uint32_t)(wn * 64 + nf * 16)) ^ ((uint32_t)(lane & 7) << 4));
                LDSM2T(bh, Bth + boff);
                LDSM2T(bl, Btl + boff);
                #pragma unroll
                for (int mf = 0; mf < 4; mf++) {
                    MMA_BF16(acc[mf][nf], ah[mf], bh);
                    MMA_BF16(acc[mf][nf], ah[mf], bl);
                    MMA_BF16(acc[mf][nf], al[mf], bh);
                }
            }
        }

        if (c + 1 < NCH) {
            char* nbh = dsm + (buf ^ 1) * STAGE_BYTES + A_TILE_BYTES;
            char* nbl = nbh + B_TILE_BYTES;
            float4 bq[4] = {bq0, bq1, bq2, bq3};
            #pragma unroll
            for (int c4 = 0; c4 < 4; c4++) {
                float4 f = bq[c4];
                __nv_bfloat162 h01 = __floats2bfloat162_rn(f.x, f.y);
                __nv_bfloat162 h23 = __floats2bfloat162_rn(f.z, f.w);
                __nv_bfloat162 l01 = __floats2bfloat162_rn(f.x - __bfloat162float(__low2bfloat16(h01)),
                                                           f.y - __bfloat162float(__high2bfloat16(h01)));
                __nv_bfloat162 l23 = __floats2bfloat162_rn(f.z - __bfloat162float(__low2bfloat16(h23)),
                                                           f.w - __bfloat162float(__high2bfloat16(h23)));
                uint32_t off = dBrow + (((uint32_t)(seg * 8 + c4 * 64)) ^ maskB);
                *(uint2*)(nbh + off) = make_uint2(*(uint32_t*)&h01, *(uint32_t*)&h23);
                *(uint2*)(nbl + off) = make_uint2(*(uint32_t*)&l01, *(uint32_t*)&l23);
            }
            CP_WAIT(0);
        }
        __syncthreads();
    }

    // ---- epilogue
    #pragma unroll
    for (int mf = 0; mf < 4; mf++) {
        int row0 = mtile * 128 + wm * 64 + mf * 16 + (lane >> 2);
        int row1 = row0 + 8;
        #pragma unroll
        for (int nf = 0; nf < 4; nf++) {
            int n = ntile * 128 + wn * 32 + nf * 8 + 2 * (lane & 3);
            if (FIRST) {
                float b0v = bias[(size_t)e * NTOT + n];
                float b1v = bias[(size_t)e * NTOT + n + 1];
                #pragma unroll
                for (int h = 0; h < 2; h++) {
                    int row = h ? row1 : row0;
                    float v0 = gelu_tanh(acc[mf][nf][2 * h + 0] + b0v);
                    float v1 = gelu_tanh(acc[mf][nf][2 * h + 1] + b1v);
                    __nv_bfloat162 h2 = __floats2bfloat162_rn(v0, v1);
                    float f0 = __bfloat162float(__low2bfloat16(h2));
                    float f1 = __bfloat162float(__high2bfloat16(h2));
                    __nv_bfloat162 l2 = __floats2bfloat162_rn(v0 - f0, v1 - f1);
                    *(uint32_t*)(g_hh + (size_t)row * F_DIM + n) = *(uint32_t*)&h2;
                    *(uint32_t*)(g_hl + (size_t)row * F_DIM + n) = *(uint32_t*)&l2;
                }
            } else {
                *(float2*)(g_outs + (size_t)row0 * D_DIM + n) =
                    make_float2(acc[mf][nf][0], acc[mf][nf][1]);
                *(float2*)(g_outs + (size_t)row1 * D_DIM + n) =
                    make_float2(acc[mf][nf][2], acc[mf][nf][3]);
            }
        }
    }
}

// ---------------- combine ----------------
__global__ __launch_bounds__(128) void combine_kernel(const float* __restrict__ b2,
                                                      float* __restrict__ out) {
    int t = blockIdx.x;
    int d4 = threadIdx.x;
    int s0 = g_token_slot[2 * t + 0];
    int s1 = g_token_slot[2 * t + 1];
    int e0 = g_slot_expert[s0], e1 = g_slot_expert[s1];
    float w0 = g_slot_w[s0], w1 = g_slot_w[s1];
    float4 o0 = ((const float4*)(g_outs + (size_t)s0 * D_DIM))[d4];
    float4 o1 = ((const float4*)(g_outs + (size_t)s1 * D_DIM))[d4];
    float4 c0 = ((const float4*)(b2 + (size_t)e0 * D_DIM))[d4];
    float4 c1 = ((const float4*)(b2 + (size_t)e1 * D_DIM))[d4];
    float4 r;
    r.x = w0 * (o0.x + c0.x) + w1 * (o1.x + c1.x);
    r.y = w0 * (o0.y + c0.y) + w1 * (o1.y + c1.y);
    r.z = w0 * (o0.z + c0.z) + w1 * (o1.z + c1.z);
    r.w = w0 * (o0.w + c0.w) + w1 * (o1.w + c1.w);
    ((float4*)(out + (size_t)t * D_DIM))[d4] = r;
}

// ---------------- launch ----------------
extern "C" void kernel_launch(void* const* d_in, const int* in_sizes, int n_in,
                              void* d_out, int out_size) {
    const float* x      = (const float*)d_in[0];
    const float* flow   = (const float*)d_in[1];
    const float* avgq   = (const float*)d_in[2];
    const float* deltas = (const float*)d_in[3];
    const float* Wr     = (const float*)d_in[4];
    const float* W1     = (const float*)d_in[5];
    const float* b1     = (const float*)d_in[6];
    const float* W2     = (const float*)d_in[7];
    const float* b2     = (const float*)d_in[8];
    const float* Wf     = (const float*)d_in[9];
    const float* Wd     = (const float*)d_in[10];
    float* out = (float*)d_out;

    float* aux_ptr = (out_size > T_TOK * D_DIM) ? (out + (size_t)T_TOK * D_DIM) : nullptr;

    cudaFuncSetAttribute(gemm_mma<D_DIM, true>,  cudaFuncAttributeMaxDynamicSharedMemorySize, DSMEM_BYTES);
    cudaFuncSetAttribute(gemm_mma<F_DIM, false>, cudaFuncAttributeMaxDynamicSharedMemorySize, DSMEM_BYTES);

    init_kernel<<<(CAP + 255) / 256, 256>>>();
    router_kernel<<<RBLOCKS, 256>>>(x, Wr);
    scan_kernel<<<1, 256>>>(aux_ptr);
    assign_kernel<<<(T_TOK + 255) / 256, 256>>>();
    gather_kernel<<<CAP, 128>>>(x, flow, avgq, deltas, Wf, Wd);
    gemm_mma<D_DIM, true><<<dim3(F_DIM / 128, MTILES), 256, DSMEM_BYTES>>>(W1, b1);
    gemm_mma<F_DIM, false><<<dim3(D_DIM / 128, MTILES), 256, DSMEM_BYTES>>>(W2, nullptr);
    combine_kernel<<<T_TOK, 128>>>(b2, out);
}